// round 8
// baseline (speedup 1.0000x reference)
#include <cuda_runtime.h>
#include <math.h>

#define S_  1024
#define B_  128
#define F_  202
#define H_  100
#define K_  19
#define N2_ 200   // 2*H

// ---- scratch (device globals: no runtime allocation allowed) ----
__device__ float g_xp[(size_t)S_ * B_ * N2_];  // input projections, both dirs
__device__ float g_h [(size_t)S_ * B_ * N2_];  // hidden states [hf | hb]
__device__ float g_em[(size_t)S_ * B_ * K_];   // softmax emissions

// ---- packed dual-fp32 helpers (sm_103a f32x2 pipe) ----
static __device__ __forceinline__ unsigned long long ffma2_(
    unsigned long long a, unsigned long long b, unsigned long long c)
{
    unsigned long long d;
    asm("fma.rn.f32x2 %0, %1, %2, %3;" : "=l"(d) : "l"(a), "l"(b), "l"(c));
    return d;
}
static __device__ __forceinline__ unsigned long long addf2_(
    unsigned long long a, unsigned long long b)
{
    unsigned long long d;
    asm("add.rn.f32x2 %0, %1, %2;" : "=l"(d) : "l"(a), "l"(b));
    return d;
}
static __device__ __forceinline__ float lo_(unsigned long long v) {
    return __uint_as_float((unsigned)(v & 0xffffffffull));
}
static __device__ __forceinline__ float hi_(unsigned long long v) {
    return __uint_as_float((unsigned)(v >> 32));
}
static __device__ __forceinline__ unsigned long long pack2_(float lo, float hi) {
    unsigned long long r;
    asm("mov.b64 %0, {%1, %2};" : "=l"(r) : "f"(lo), "f"(hi));
    return r;
}
// predicated stores (single @p instruction, no BSSY/BSYNC envelope)
static __device__ __forceinline__ void sts_pred_(int pred, unsigned addr, float v) {
    asm volatile("{ .reg .pred p; setp.ne.s32 p, %0, 0; @p st.shared.f32 [%1], %2; }"
                 :: "r"(pred), "r"(addr), "f"(v));
}
static __device__ __forceinline__ void stg_pred_(int pred, float* ptr, float v) {
    asm volatile("{ .reg .pred p; setp.ne.s32 p, %0, 0; @p st.global.f32 [%1], %2; }"
                 :: "r"(pred), "l"(ptr), "f"(v));
}
static __device__ __forceinline__ unsigned smem_u32_(const void* p) {
    unsigned a;
    asm("{ .reg .u64 t; cvta.to.shared.u64 t, %1; cvt.u32.u64 %0, t; }" : "=r"(a) : "l"(p));
    return a;
}
static __device__ __forceinline__ void cpasync8_(unsigned dst, const float* src) {
    asm volatile("cp.async.ca.shared.global [%0], [%1], 8;" :: "r"(dst), "l"(src));
}
static __device__ __forceinline__ void barn_(int id, int cnt) {
    asm volatile("bar.sync %0, %1;" :: "r"(id), "r"(cnt) : "memory");
}

// profiling-slot spacer (ncu captures the 4th app launch; keep it rnn)
__global__ void noop_kernel() {}

// =====================================================================
// Kernel 1: persistent input projection (unchanged from R7).
// =====================================================================
#define PG_DIR  74
#define PG_G    148
#define PJ_T    640
#define AS4_    51
#define OFF_A0  0
#define OFF_A1  (64 * 204)
#define OFF_B   (2 * 64 * 204)
#define OFF_EP  (OFF_B + 100 * 204)
#define PJ_SMEM ((OFF_EP + 64 * 101) * 4)
#define NTILES  2048

__global__ __launch_bounds__(PJ_T, 1) void proj_kernel(
    const float* __restrict__ x,
    const float* __restrict__ Wf, const float* __restrict__ Wb,
    const float* __restrict__ bihf, const float* __restrict__ bhhf,
    const float* __restrict__ bihb, const float* __restrict__ bhhb)
{
    extern __shared__ __align__(16) float smf[];
    const int tid = threadIdx.x;
    const int dir = (blockIdx.x >= PG_DIR) ? 1 : 0;
    const int cid = blockIdx.x - dir * PG_DIR;
    const float* W   = dir ? Wb   : Wf;
    const float* bih = dir ? bihb : bihf;
    const float* bhh = dir ? bhhb : bhhf;

    if (tid < 256) {
        int r = tid >> 1, c = 202 + (tid & 1);
        smf[OFF_A0 + r * 204 + c] = 0.f;
    }

    const unsigned abase0 = smem_u32_(smf + OFF_A0);
    const unsigned abase1 = smem_u32_(smf + OFF_A1);

    {
        const float* src = x + (size_t)cid * 64 * F_;
        #pragma unroll
        for (int q = 0; q < 11; q++) {
            int e = tid + q * PJ_T;
            if (e < 6464) {
                int r = e / 101, c = e - r * 101;
                cpasync8_(abase0 + (unsigned)(r * 204 + c * 2) * 4u, src + r * F_ + c * 2);
            }
        }
        asm volatile("cp.async.commit_group;");
    }

    for (int e = tid; e < 100 * 204; e += PJ_T) {
        int n = e / 204, f = e - n * 204;
        smf[OFF_B + e] = (f < F_) ? W[n * F_ + f] : 0.f;
    }

    const int tx = tid & 31;
    const int w  = tid >> 5;
    float bias_j[5];
    #pragma unroll
    for (int j = 0; j < 5; j++) { int c = w + 20 * j; bias_j[j] = bih[c] + bhh[c]; }

    const ulonglong2* B2 = (const ulonglong2*)(smf + OFF_B);
    float* ep = smf + OFF_EP;

    int cur = 0;
    for (int mt = cid; mt < NTILES; mt += PG_DIR) {
        int nt = mt + PG_DIR;
        if (nt < NTILES) {
            const float* src = x + (size_t)nt * 64 * F_;
            const unsigned ab = cur ? abase0 : abase1;
            #pragma unroll
            for (int q = 0; q < 11; q++) {
                int e = tid + q * PJ_T;
                if (e < 6464) {
                    int r = e / 101, c = e - r * 101;
                    cpasync8_(ab + (unsigned)(r * 204 + c * 2) * 4u, src + r * F_ + c * 2);
                }
            }
        }
        asm volatile("cp.async.commit_group;");
        asm volatile("cp.async.wait_group 1;");
        __syncthreads();

        const ulonglong2* A2 = (const ulonglong2*)(smf + (cur ? OFF_A1 : OFF_A0));
        unsigned long long acc2[2][5];
        #pragma unroll
        for (int i = 0; i < 2; i++)
            #pragma unroll
            for (int j = 0; j < 5; j++) acc2[i][j] = 0ull;

        #pragma unroll 3
        for (int kk = 0; kk < 51; kk++) {
            ulonglong2 a0 = A2[tx * AS4_ + kk];
            ulonglong2 a1 = A2[(tx + 32) * AS4_ + kk];
            ulonglong2 b[5];
            #pragma unroll
            for (int j = 0; j < 5; j++) b[j] = B2[(w + 20 * j) * AS4_ + kk];
            #pragma unroll
            for (int j = 0; j < 5; j++) {
                acc2[0][j] = ffma2_(a0.x, b[j].x, acc2[0][j]);
                acc2[0][j] = ffma2_(a0.y, b[j].y, acc2[0][j]);
                acc2[1][j] = ffma2_(a1.x, b[j].x, acc2[1][j]);
                acc2[1][j] = ffma2_(a1.y, b[j].y, acc2[1][j]);
            }
        }

        #pragma unroll
        for (int j = 0; j < 5; j++) {
            int c = w + 20 * j;
            ep[tx * 101 + c]        = lo_(acc2[0][j]) + hi_(acc2[0][j]) + bias_j[j];
            ep[(tx + 32) * 101 + c] = lo_(acc2[1][j]) + hi_(acc2[1][j]) + bias_j[j];
        }
        __syncthreads();
        {
            float* gout = g_xp + (size_t)(mt * 64) * N2_ + dir * H_;
            #pragma unroll
            for (int q = 0; q < 10; q++) {
                int e = tid + q * PJ_T;
                int r = e / 100, c = e - r * 100;
                gout[(size_t)r * N2_ + c] = ep[r * 101 + c];
            }
        }
        __syncthreads();
        cur ^= 1;
    }
}

// =====================================================================
// Kernel 2: recurrent scans. 128-thr CTA = TWO chains (64 thr each).
//   Each lane owns 2 output rows (t64, t64+64); weights in registers;
//   h exchange via SMEM broadcast; per-chain NAMED barriers so the two
//   chains never false-couple. 1 warp/SMSP -> contention-free issue.
// =====================================================================
__global__ __launch_bounds__(128) void rnn_kernel(
    const float* __restrict__ Whhf, const float* __restrict__ Whhb)
{
    const int tid   = threadIdx.x;
    const int c2    = tid >> 6;                // chain slot in CTA (0/1)
    const int t64   = tid & 63;
    const int chain = blockIdx.x * 2 + c2;     // 0..255
    const int dir   = chain >> 7;
    const int b     = chain & 127;

    const int r0   = t64;                      // always < 100
    const int r1   = t64 + 64;
    const int act1 = (r1 < H_) ? 1 : 0;
    const int r1c  = act1 ? r1 : (H_ - 1);

    __shared__ __align__(16) float hs[2][2][104];   // [chain][phase][h]

    const float* Whh = dir ? Whhb : Whhf;
    unsigned long long wA[50], wB[50];
    {
        const ulonglong2* wa = (const ulonglong2*)(Whh + r0 * H_);
        const ulonglong2* wb = (const ulonglong2*)(Whh + r1c * H_);
        #pragma unroll
        for (int k = 0; k < 25; k++) {
            ulonglong2 ta = wa[k]; wA[2*k] = ta.x; wA[2*k+1] = ta.y;
            ulonglong2 tb = wb[k]; wB[2*k] = tb.x; wB[2*k+1] = tb.y;
        }
    }
    if (t64 < 52) {
        hs[c2][0][t64 * 2]     = 0.f; hs[c2][0][t64 * 2 + 1] = 0.f;
        hs[c2][1][t64 * 2]     = 0.f; hs[c2][1][t64 * 2 + 1] = 0.f;
    }
    const int bid = 1 + c2;
    barn_(bid, 64);

    const unsigned hbase = smem_u32_(&hs[c2][0][0]);
    const float* xpA = g_xp + (size_t)b * N2_ + dir * H_ + r0;
    const float* xpB = g_xp + (size_t)b * N2_ + dir * H_ + r1c;
    float*       hgA = g_h  + (size_t)b * N2_ + dir * H_ + r0;
    float*       hgB = g_h  + (size_t)b * N2_ + dir * H_ + r1c;
    const int s0 = dir ? (S_ - 1) : 0;
    const int ds = dir ? -1 : 1;
    const int STRIDE = B_ * N2_;  // 25600

    float xqA[2], xqB[2];
    #pragma unroll
    for (int q = 0; q < 2; q++) {
        xqA[q] = xpA[(size_t)(s0 + ds * q) * STRIDE];
        xqB[q] = xpB[(size_t)(s0 + ds * q) * STRIDE];
    }

    int p = 0;
    #pragma unroll 2
    for (int t = 0; t < S_; t++) {
        const int s = s0 + ds * t;
        const float xA = xqA[t & 1];
        const float xB = xqB[t & 1];
        int tp = t + 2; tp = (tp < S_) ? tp : (S_ - 1);
        xqA[t & 1] = xpA[(size_t)(s0 + ds * tp) * STRIDE];
        xqB[t & 1] = xpB[(size_t)(s0 + ds * tp) * STRIDE];

        unsigned long long aA[4], aB[4];
        aA[0] = pack2_(xA, 0.f); aB[0] = pack2_(xB, 0.f);
        #pragma unroll
        for (int q = 1; q < 4; q++) { aA[q] = 0ull; aB[q] = 0ull; }

        const ulonglong2* hv2 = (const ulonglong2*)(hs[c2][p]);
        #pragma unroll
        for (int k = 0; k < 25; k++) {
            ulonglong2 h2 = hv2[k];
            aA[(2*k)     & 3] = ffma2_(wA[2*k],     h2.x, aA[(2*k)     & 3]);
            aA[(2*k + 1) & 3] = ffma2_(wA[2*k + 1], h2.y, aA[(2*k + 1) & 3]);
            aB[(2*k)     & 3] = ffma2_(wB[2*k],     h2.x, aB[(2*k)     & 3]);
            aB[(2*k + 1) & 3] = ffma2_(wB[2*k + 1], h2.y, aB[(2*k + 1) & 3]);
        }
        unsigned long long rA = addf2_(addf2_(aA[0], aA[2]), addf2_(aA[1], aA[3]));
        unsigned long long rB = addf2_(addf2_(aB[0], aB[2]), addf2_(aB[1], aB[3]));
        float accA = lo_(rA) + hi_(rA);
        float accB = lo_(rB) + hi_(rB);

        // tanh(x) = 1 - 2/(e^{2x}+1); inf-safe, ~1e-7 abs err
        float eA = __expf(accA + accA);
        float eB = __expf(accB + accB);
        float hA = 1.f - __fdividef(2.f, eA + 1.f);
        float hB = 1.f - __fdividef(2.f, eB + 1.f);

        hs[c2][p ^ 1][r0] = hA;                               // r0 < 100: plain store
        sts_pred_(act1, hbase + (unsigned)((p ^ 1) * 104 + r1) * 4u, hB);
        hgA[(size_t)s * STRIDE] = hA;
        stg_pred_(act1, hgB + (size_t)s * STRIDE, hB);
        barn_(bid, 64);
        p ^= 1;
    }
}

// =====================================================================
// Kernel 3: logits + softmax -> emissions. Thread per (s,b) row.
// =====================================================================
__global__ __launch_bounds__(256) void logits_kernel(
    const float* __restrict__ Wout, const float* __restrict__ bout)
{
    __shared__ __align__(16) float wt[N2_ * 20];   // W_out^T, K padded 19->20
    const int tid = threadIdx.x;
    for (int e = tid; e < N2_ * 20; e += 256) {
        int f = e / 20, k = e - f * 20;
        wt[e] = (k < K_) ? Wout[k * N2_ + f] : 0.f;
    }
    __syncthreads();

    const int m = blockIdx.x * 256 + tid;
    const float4* hp = (const float4*)(g_h + (size_t)m * N2_);
    const ulonglong2* wt2 = (const ulonglong2*)wt;

    unsigned long long acc2[10];
    #pragma unroll
    for (int q = 0; q < 10; q++) acc2[q] = 0ull;

    for (int f4 = 0; f4 < 50; f4++) {
        float4 hv = __ldg(&hp[f4]);
        float hh[4] = {hv.x, hv.y, hv.z, hv.w};
        #pragma unroll
        for (int c = 0; c < 4; c++) {
            const int f = f4 * 4 + c;
            const unsigned long long hb = pack2_(hh[c], hh[c]);
            #pragma unroll
            for (int q = 0; q < 5; q++) {
                ulonglong2 wv = wt2[f * 5 + q];
                acc2[2*q]     = ffma2_(hb, wv.x, acc2[2*q]);
                acc2[2*q + 1] = ffma2_(hb, wv.y, acc2[2*q + 1]);
            }
        }
    }

    float acc[20];
    #pragma unroll
    for (int q = 0; q < 10; q++) { acc[2*q] = lo_(acc2[q]); acc[2*q+1] = hi_(acc2[q]); }

    float mx = -1e30f;
    #pragma unroll
    for (int k = 0; k < K_; k++) { acc[k] += __ldg(&bout[k]); mx = fmaxf(mx, acc[k]); }
    float sum = 0.f;
    #pragma unroll
    for (int k = 0; k < K_; k++) { acc[k] = __expf(acc[k] - mx); sum += acc[k]; }
    const float inv = 1.f / sum;
    float* e = g_em + (size_t)m * K_;
    #pragma unroll
    for (int k = 0; k < K_; k++) e[k] = acc[k] * inv;
}

// =====================================================================
// Kernel 4: Viterbi decode. Warp per sequence; tree argmax.
// =====================================================================
__global__ __launch_bounds__(256) void viterbi_kernel(
    const float* __restrict__ start, const float* __restrict__ endt,
    const float* __restrict__ trans, float* __restrict__ out)
{
    __shared__ unsigned char hist[8][127][20];
    const int w    = threadIdx.x >> 5;
    const int lane = threadIdx.x & 31;
    const int n    = blockIdx.x * 8 + w;
    const int j    = lane;
    const bool act = (j < K_);

    float tr[K_];
    #pragma unroll
    for (int i = 0; i < K_; i++) tr[i] = act ? trans[i * K_ + j] : 0.f;

    const float* emn = g_em + (size_t)n * B_ * K_;
    float score = act ? (start[j] + emn[j]) : -1e30f;

    for (int t = 1; t < B_; t++) {
        const float e = act ? emn[t * K_ + j] : 0.f;
        float bv[K_]; int bi[K_];
        #pragma unroll
        for (int i = 0; i < K_; i++) {
            float si = __shfl_sync(0xffffffffu, score, i);
            bv[i] = si + tr[i];
            bi[i] = i;
        }
        #pragma unroll
        for (int st = 1; st < 32; st <<= 1)
            #pragma unroll
            for (int i = 0; i + st < K_; i += 2 * st) {
                bool take = (bv[i + st] > bv[i]);
                bv[i] = take ? bv[i + st] : bv[i];
                bi[i] = take ? bi[i + st] : bi[i];
            }
        if (act) hist[w][t - 1][j] = (unsigned char)bi[0];
        score = bv[0] + e;
    }

    float v  = act ? (score + endt[j]) : -1e30f;
    int  idx = j;
    #pragma unroll
    for (int off = 16; off; off >>= 1) {
        float ov = __shfl_down_sync(0xffffffffu, v, off);
        int   oi = __shfl_down_sync(0xffffffffu, idx, off);
        if (ov > v || (ov == v && oi < idx)) { v = ov; idx = oi; }
    }
    __syncwarp();

    if (lane == 0) {
        int tag = idx;
        float* o = out + (size_t)n * B_;
        o[B_ - 1] = (float)tag;
        for (int t = B_ - 2; t >= 0; t--) {
            tag  = hist[w][t][tag];
            o[t] = (float)tag;
        }
    }
}

// =====================================================================
extern "C" void kernel_launch(void* const* d_in, const int* in_sizes, int n_in,
                              void* d_out, int out_size)
{
    const float* x     = (const float*)d_in[0];
    const float* Wihf  = (const float*)d_in[1];
    const float* Whhf  = (const float*)d_in[2];
    const float* bihf  = (const float*)d_in[3];
    const float* bhhf  = (const float*)d_in[4];
    const float* Wihb  = (const float*)d_in[5];
    const float* Whhb  = (const float*)d_in[6];
    const float* bihb  = (const float*)d_in[7];
    const float* bhhb  = (const float*)d_in[8];
    const float* Wout  = (const float*)d_in[9];
    const float* bout  = (const float*)d_in[10];
    const float* start = (const float*)d_in[11];
    const float* endt  = (const float*)d_in[12];
    const float* trans = (const float*)d_in[13];
    float* out = (float*)d_out;

    cudaFuncSetAttribute(proj_kernel, cudaFuncAttributeMaxDynamicSharedMemorySize, PJ_SMEM);

    // spacers: keep rnn_kernel in the ncu capture slot (4th app launch)
    noop_kernel<<<1, 32>>>();
    noop_kernel<<<1, 32>>>();
    proj_kernel<<<PG_G, PJ_T, PJ_SMEM>>>(x, Wihf, Wihb, bihf, bhhf, bihb, bhhb);
    rnn_kernel<<<B_, 128>>>(Whhf, Whhb);
    logits_kernel<<<(S_ * B_) / 256, 256>>>(Wout, bout);
    viterbi_kernel<<<S_ / 8, 256>>>(start, endt, trans, out);
}

// round 9
// speedup vs baseline: 1.0445x; 1.0445x over previous
#include <cuda_runtime.h>
#include <math.h>

#define S_  1024
#define B_  128
#define F_  202
#define H_  100
#define K_  19
#define N2_ 200   // 2*H

// ---- scratch (device globals: no runtime allocation allowed) ----
__device__ float g_xp[(size_t)S_ * B_ * N2_];  // input projections, both dirs
__device__ float g_h [(size_t)S_ * B_ * N2_];  // hidden states [hf | hb]
__device__ float g_em[(size_t)S_ * B_ * K_];   // softmax emissions

// ---- packed dual-fp32 helpers (sm_103a f32x2 pipe) ----
static __device__ __forceinline__ unsigned long long ffma2_(
    unsigned long long a, unsigned long long b, unsigned long long c)
{
    unsigned long long d;
    asm("fma.rn.f32x2 %0, %1, %2, %3;" : "=l"(d) : "l"(a), "l"(b), "l"(c));
    return d;
}
static __device__ __forceinline__ unsigned long long addf2_(
    unsigned long long a, unsigned long long b)
{
    unsigned long long d;
    asm("add.rn.f32x2 %0, %1, %2;" : "=l"(d) : "l"(a), "l"(b));
    return d;
}
static __device__ __forceinline__ float lo_(unsigned long long v) {
    return __uint_as_float((unsigned)(v & 0xffffffffull));
}
static __device__ __forceinline__ float hi_(unsigned long long v) {
    return __uint_as_float((unsigned)(v >> 32));
}
static __device__ __forceinline__ unsigned long long pack2_(float lo, float hi) {
    unsigned long long r;
    asm("mov.b64 %0, {%1, %2};" : "=l"(r) : "f"(lo), "f"(hi));
    return r;
}
// predicated stores (single @p instruction, no BSSY/BSYNC envelope)
static __device__ __forceinline__ void sts_pred_(int pred, unsigned addr, float v) {
    asm volatile("{ .reg .pred p; setp.ne.s32 p, %0, 0; @p st.shared.f32 [%1], %2; }"
                 :: "r"(pred), "r"(addr), "f"(v));
}
static __device__ __forceinline__ void stg_pred_(int pred, float* ptr, float v) {
    asm volatile("{ .reg .pred p; setp.ne.s32 p, %0, 0; @p st.global.f32 [%1], %2; }"
                 :: "r"(pred), "l"(ptr), "f"(v));
}
static __device__ __forceinline__ unsigned smem_u32_(const void* p) {
    unsigned a;
    asm("{ .reg .u64 t; cvta.to.shared.u64 t, %1; cvt.u32.u64 %0, t; }" : "=r"(a) : "l"(p));
    return a;
}
static __device__ __forceinline__ void cpasync8_(unsigned dst, const float* src) {
    asm volatile("cp.async.ca.shared.global [%0], [%1], 8;" :: "r"(dst), "l"(src));
}
static __device__ __forceinline__ void barn_(int id, int cnt) {
    asm volatile("bar.sync %0, %1;" :: "r"(id), "r"(cnt) : "memory");
}

// profiling-slot spacer (ncu captures the 4th app launch; keep it rnn)
__global__ void noop_kernel() {}

// =====================================================================
// Kernel 1: persistent input projection (unchanged from R7).
// =====================================================================
#define PG_DIR  74
#define PG_G    148
#define PJ_T    640
#define AS4_    51
#define OFF_A0  0
#define OFF_A1  (64 * 204)
#define OFF_B   (2 * 64 * 204)
#define OFF_EP  (OFF_B + 100 * 204)
#define PJ_SMEM ((OFF_EP + 64 * 101) * 4)
#define NTILES  2048

__global__ __launch_bounds__(PJ_T, 1) void proj_kernel(
    const float* __restrict__ x,
    const float* __restrict__ Wf, const float* __restrict__ Wb,
    const float* __restrict__ bihf, const float* __restrict__ bhhf,
    const float* __restrict__ bihb, const float* __restrict__ bhhb)
{
    extern __shared__ __align__(16) float smf[];
    const int tid = threadIdx.x;
    const int dir = (blockIdx.x >= PG_DIR) ? 1 : 0;
    const int cid = blockIdx.x - dir * PG_DIR;
    const float* W   = dir ? Wb   : Wf;
    const float* bih = dir ? bihb : bihf;
    const float* bhh = dir ? bhhb : bhhf;

    if (tid < 256) {
        int r = tid >> 1, c = 202 + (tid & 1);
        smf[OFF_A0 + r * 204 + c] = 0.f;
    }

    const unsigned abase0 = smem_u32_(smf + OFF_A0);
    const unsigned abase1 = smem_u32_(smf + OFF_A1);

    {
        const float* src = x + (size_t)cid * 64 * F_;
        #pragma unroll
        for (int q = 0; q < 11; q++) {
            int e = tid + q * PJ_T;
            if (e < 6464) {
                int r = e / 101, c = e - r * 101;
                cpasync8_(abase0 + (unsigned)(r * 204 + c * 2) * 4u, src + r * F_ + c * 2);
            }
        }
        asm volatile("cp.async.commit_group;");
    }

    for (int e = tid; e < 100 * 204; e += PJ_T) {
        int n = e / 204, f = e - n * 204;
        smf[OFF_B + e] = (f < F_) ? W[n * F_ + f] : 0.f;
    }

    const int tx = tid & 31;
    const int w  = tid >> 5;
    float bias_j[5];
    #pragma unroll
    for (int j = 0; j < 5; j++) { int c = w + 20 * j; bias_j[j] = bih[c] + bhh[c]; }

    const ulonglong2* B2 = (const ulonglong2*)(smf + OFF_B);
    float* ep = smf + OFF_EP;

    int cur = 0;
    for (int mt = cid; mt < NTILES; mt += PG_DIR) {
        int nt = mt + PG_DIR;
        if (nt < NTILES) {
            const float* src = x + (size_t)nt * 64 * F_;
            const unsigned ab = cur ? abase0 : abase1;
            #pragma unroll
            for (int q = 0; q < 11; q++) {
                int e = tid + q * PJ_T;
                if (e < 6464) {
                    int r = e / 101, c = e - r * 101;
                    cpasync8_(ab + (unsigned)(r * 204 + c * 2) * 4u, src + r * F_ + c * 2);
                }
            }
        }
        asm volatile("cp.async.commit_group;");
        asm volatile("cp.async.wait_group 1;");
        __syncthreads();

        const ulonglong2* A2 = (const ulonglong2*)(smf + (cur ? OFF_A1 : OFF_A0));
        unsigned long long acc2[2][5];
        #pragma unroll
        for (int i = 0; i < 2; i++)
            #pragma unroll
            for (int j = 0; j < 5; j++) acc2[i][j] = 0ull;

        #pragma unroll 3
        for (int kk = 0; kk < 51; kk++) {
            ulonglong2 a0 = A2[tx * AS4_ + kk];
            ulonglong2 a1 = A2[(tx + 32) * AS4_ + kk];
            ulonglong2 b[5];
            #pragma unroll
            for (int j = 0; j < 5; j++) b[j] = B2[(w + 20 * j) * AS4_ + kk];
            #pragma unroll
            for (int j = 0; j < 5; j++) {
                acc2[0][j] = ffma2_(a0.x, b[j].x, acc2[0][j]);
                acc2[0][j] = ffma2_(a0.y, b[j].y, acc2[0][j]);
                acc2[1][j] = ffma2_(a1.x, b[j].x, acc2[1][j]);
                acc2[1][j] = ffma2_(a1.y, b[j].y, acc2[1][j]);
            }
        }

        #pragma unroll
        for (int j = 0; j < 5; j++) {
            int c = w + 20 * j;
            ep[tx * 101 + c]        = lo_(acc2[0][j]) + hi_(acc2[0][j]) + bias_j[j];
            ep[(tx + 32) * 101 + c] = lo_(acc2[1][j]) + hi_(acc2[1][j]) + bias_j[j];
        }
        __syncthreads();
        {
            float* gout = g_xp + (size_t)(mt * 64) * N2_ + dir * H_;
            #pragma unroll
            for (int q = 0; q < 10; q++) {
                int e = tid + q * PJ_T;
                int r = e / 100, c = e - r * 100;
                gout[(size_t)r * N2_ + c] = ep[r * 101 + c];
            }
        }
        __syncthreads();
        cur ^= 1;
    }
}

// =====================================================================
// Kernel 2: recurrent scans. 128-thr CTA = TWO chains (64 thr each),
//   per-chain named barriers, 1 warp/SMSP. Row r0 weights in REGISTERS
//   (50 packed), row r1 weights in SMEM (shared tile, rows 64..99 --
//   both chains of a CTA always have the same direction). regs ~150,
//   no spills (R8's 255-reg spill bug fixed).
// =====================================================================
__global__ __launch_bounds__(128, 1) void rnn_kernel(
    const float* __restrict__ Whhf, const float* __restrict__ Whhb)
{
    const int tid   = threadIdx.x;
    const int c2    = tid >> 6;                // chain slot in CTA (0/1)
    const int t64   = tid & 63;
    const int chain = blockIdx.x * 2 + c2;     // 0..255
    const int dir   = chain >> 7;              // same for both chains in CTA
    const int b     = chain & 127;

    const int r0   = t64;                      // < 100 always
    const int r1   = t64 + 64;                 // 64..127
    const int act1 = (r1 < H_) ? 1 : 0;
    const int r1c  = act1 ? r1 : (H_ - 1);

    __shared__ __align__(16) float hs[2][2][104];     // [chain][phase][h]
    __shared__ __align__(16) float wsh[36 * 100];     // Whh rows 64..99

    const float* Whh = dir ? Whhb : Whhf;
    unsigned long long wA[50];
    {
        const ulonglong2* wa = (const ulonglong2*)(Whh + r0 * H_);
        #pragma unroll
        for (int k = 0; k < 25; k++) { ulonglong2 t = wa[k]; wA[2*k] = t.x; wA[2*k+1] = t.y; }
    }
    for (int e = tid; e < 3600; e += 128) wsh[e] = Whh[64 * H_ + e];
    if (tid < 104) {
        hs[0][0][tid] = 0.f; hs[0][1][tid] = 0.f;
        hs[1][0][tid] = 0.f; hs[1][1][tid] = 0.f;
    }
    __syncthreads();

    const ulonglong2* wB2 = (const ulonglong2*)wsh + (r1c - 64) * 25;
    const unsigned hbase = smem_u32_(&hs[c2][0][0]);
    const float* xpA = g_xp + (size_t)b * N2_ + dir * H_ + r0;
    const float* xpB = g_xp + (size_t)b * N2_ + dir * H_ + r1c;
    float*       hgA = g_h  + (size_t)b * N2_ + dir * H_ + r0;
    float*       hgB = g_h  + (size_t)b * N2_ + dir * H_ + r1c;
    const int s0 = dir ? (S_ - 1) : 0;
    const int ds = dir ? -1 : 1;
    const int STRIDE = B_ * N2_;  // 25600
    const int bid = 1 + c2;

    float xqA[4], xqB[4];
    #pragma unroll
    for (int q = 0; q < 4; q++) {
        xqA[q] = xpA[(size_t)(s0 + ds * q) * STRIDE];
        xqB[q] = xpB[(size_t)(s0 + ds * q) * STRIDE];
    }

    int p = 0;
    #pragma unroll 4
    for (int t = 0; t < S_; t++) {
        const int s = s0 + ds * t;
        const float xA = xqA[t & 3];
        const float xB = xqB[t & 3];
        int tp = t + 4; tp = (tp < S_) ? tp : (S_ - 1);
        xqA[t & 3] = xpA[(size_t)(s0 + ds * tp) * STRIDE];
        xqB[t & 3] = xpB[(size_t)(s0 + ds * tp) * STRIDE];

        unsigned long long aA[4], aB[4];
        aA[0] = pack2_(xA, 0.f); aB[0] = pack2_(xB, 0.f);
        #pragma unroll
        for (int q = 1; q < 4; q++) { aA[q] = 0ull; aB[q] = 0ull; }

        const ulonglong2* hv2 = (const ulonglong2*)(hs[c2][p]);
        #pragma unroll
        for (int k = 0; k < 25; k++) {
            ulonglong2 h2 = hv2[k];
            ulonglong2 wb = wB2[k];
            aA[(2*k)     & 3] = ffma2_(wA[2*k],     h2.x, aA[(2*k)     & 3]);
            aA[(2*k + 1) & 3] = ffma2_(wA[2*k + 1], h2.y, aA[(2*k + 1) & 3]);
            aB[(2*k)     & 3] = ffma2_(wb.x,        h2.x, aB[(2*k)     & 3]);
            aB[(2*k + 1) & 3] = ffma2_(wb.y,        h2.y, aB[(2*k + 1) & 3]);
        }
        unsigned long long rA = addf2_(addf2_(aA[0], aA[2]), addf2_(aA[1], aA[3]));
        unsigned long long rB = addf2_(addf2_(aB[0], aB[2]), addf2_(aB[1], aB[3]));
        float accA = lo_(rA) + hi_(rA);
        float accB = lo_(rB) + hi_(rB);

        // tanh(x) = 1 - 2/(e^{2x}+1); inf-safe, ~1e-7 abs err
        float eA = __expf(accA + accA);
        float eB = __expf(accB + accB);
        float hA = 1.f - __fdividef(2.f, eA + 1.f);
        float hB = 1.f - __fdividef(2.f, eB + 1.f);

        hs[c2][p ^ 1][r0] = hA;                               // r0 < 100: plain store
        sts_pred_(act1, hbase + (unsigned)((p ^ 1) * 104 + r1) * 4u, hB);
        hgA[(size_t)s * STRIDE] = hA;
        stg_pred_(act1, hgB + (size_t)s * STRIDE, hB);
        barn_(bid, 64);
        p ^= 1;
    }
}

// =====================================================================
// Kernel 3: logits + softmax -> emissions. Thread per (s,b) row.
// =====================================================================
__global__ __launch_bounds__(256) void logits_kernel(
    const float* __restrict__ Wout, const float* __restrict__ bout)
{
    __shared__ __align__(16) float wt[N2_ * 20];   // W_out^T, K padded 19->20
    const int tid = threadIdx.x;
    for (int e = tid; e < N2_ * 20; e += 256) {
        int f = e / 20, k = e - f * 20;
        wt[e] = (k < K_) ? Wout[k * N2_ + f] : 0.f;
    }
    __syncthreads();

    const int m = blockIdx.x * 256 + tid;
    const float4* hp = (const float4*)(g_h + (size_t)m * N2_);
    const ulonglong2* wt2 = (const ulonglong2*)wt;

    unsigned long long acc2[10];
    #pragma unroll
    for (int q = 0; q < 10; q++) acc2[q] = 0ull;

    for (int f4 = 0; f4 < 50; f4++) {
        float4 hv = __ldg(&hp[f4]);
        float hh[4] = {hv.x, hv.y, hv.z, hv.w};
        #pragma unroll
        for (int c = 0; c < 4; c++) {
            const int f = f4 * 4 + c;
            const unsigned long long hb = pack2_(hh[c], hh[c]);
            #pragma unroll
            for (int q = 0; q < 5; q++) {
                ulonglong2 wv = wt2[f * 5 + q];
                acc2[2*q]     = ffma2_(hb, wv.x, acc2[2*q]);
                acc2[2*q + 1] = ffma2_(hb, wv.y, acc2[2*q + 1]);
            }
        }
    }

    float acc[20];
    #pragma unroll
    for (int q = 0; q < 10; q++) { acc[2*q] = lo_(acc2[q]); acc[2*q+1] = hi_(acc2[q]); }

    float mx = -1e30f;
    #pragma unroll
    for (int k = 0; k < K_; k++) { acc[k] += __ldg(&bout[k]); mx = fmaxf(mx, acc[k]); }
    float sum = 0.f;
    #pragma unroll
    for (int k = 0; k < K_; k++) { acc[k] = __expf(acc[k] - mx); sum += acc[k]; }
    const float inv = 1.f / sum;
    float* e = g_em + (size_t)m * K_;
    #pragma unroll
    for (int k = 0; k < K_; k++) e[k] = acc[k] * inv;
}

// =====================================================================
// Kernel 4: Viterbi decode. Warp per sequence; tree argmax.
// =====================================================================
__global__ __launch_bounds__(256) void viterbi_kernel(
    const float* __restrict__ start, const float* __restrict__ endt,
    const float* __restrict__ trans, float* __restrict__ out)
{
    __shared__ unsigned char hist[8][127][20];
    const int w    = threadIdx.x >> 5;
    const int lane = threadIdx.x & 31;
    const int n    = blockIdx.x * 8 + w;
    const int j    = lane;
    const bool act = (j < K_);

    float tr[K_];
    #pragma unroll
    for (int i = 0; i < K_; i++) tr[i] = act ? trans[i * K_ + j] : 0.f;

    const float* emn = g_em + (size_t)n * B_ * K_;
    float score = act ? (start[j] + emn[j]) : -1e30f;

    for (int t = 1; t < B_; t++) {
        const float e = act ? emn[t * K_ + j] : 0.f;
        float bv[K_]; int bi[K_];
        #pragma unroll
        for (int i = 0; i < K_; i++) {
            float si = __shfl_sync(0xffffffffu, score, i);
            bv[i] = si + tr[i];
            bi[i] = i;
        }
        #pragma unroll
        for (int st = 1; st < 32; st <<= 1)
            #pragma unroll
            for (int i = 0; i + st < K_; i += 2 * st) {
                bool take = (bv[i + st] > bv[i]);
                bv[i] = take ? bv[i + st] : bv[i];
                bi[i] = take ? bi[i + st] : bi[i];
            }
        if (act) hist[w][t - 1][j] = (unsigned char)bi[0];
        score = bv[0] + e;
    }

    float v  = act ? (score + endt[j]) : -1e30f;
    int  idx = j;
    #pragma unroll
    for (int off = 16; off; off >>= 1) {
        float ov = __shfl_down_sync(0xffffffffu, v, off);
        int   oi = __shfl_down_sync(0xffffffffu, idx, off);
        if (ov > v || (ov == v && oi < idx)) { v = ov; idx = oi; }
    }
    __syncwarp();

    if (lane == 0) {
        int tag = idx;
        float* o = out + (size_t)n * B_;
        o[B_ - 1] = (float)tag;
        for (int t = B_ - 2; t >= 0; t--) {
            tag  = hist[w][t][tag];
            o[t] = (float)tag;
        }
    }
}

// =====================================================================
extern "C" void kernel_launch(void* const* d_in, const int* in_sizes, int n_in,
                              void* d_out, int out_size)
{
    const float* x     = (const float*)d_in[0];
    const float* Wihf  = (const float*)d_in[1];
    const float* Whhf  = (const float*)d_in[2];
    const float* bihf  = (const float*)d_in[3];
    const float* bhhf  = (const float*)d_in[4];
    const float* Wihb  = (const float*)d_in[5];
    const float* Whhb  = (const float*)d_in[6];
    const float* bihb  = (const float*)d_in[7];
    const float* bhhb  = (const float*)d_in[8];
    const float* Wout  = (const float*)d_in[9];
    const float* bout  = (const float*)d_in[10];
    const float* start = (const float*)d_in[11];
    const float* endt  = (const float*)d_in[12];
    const float* trans = (const float*)d_in[13];
    float* out = (float*)d_out;

    cudaFuncSetAttribute(proj_kernel, cudaFuncAttributeMaxDynamicSharedMemorySize, PJ_SMEM);

    // spacers: keep rnn_kernel in the ncu capture slot (4th app launch)
    noop_kernel<<<1, 32>>>();
    noop_kernel<<<1, 32>>>();
    proj_kernel<<<PG_G, PJ_T, PJ_SMEM>>>(x, Wihf, Wihb, bihf, bhhf, bihb, bhhb);
    rnn_kernel<<<B_, 128>>>(Whhf, Whhb);
    logits_kernel<<<(S_ * B_) / 256, 256>>>(Wout, bout);
    viterbi_kernel<<<S_ / 8, 256>>>(start, endt, trans, out);
}

// round 10
// speedup vs baseline: 1.2048x; 1.1535x over previous
#include <cuda_runtime.h>
#include <math.h>

#define S_  1024
#define B_  128
#define F_  202
#define H_  100
#define K_  19
#define N2_ 200   // 2*H

// ---- scratch (device globals: no runtime allocation allowed) ----
__device__ float g_xp[(size_t)S_ * B_ * N2_];  // input projections, both dirs
__device__ float g_h [(size_t)S_ * B_ * N2_];  // hidden states [hf | hb]
__device__ float g_em[(size_t)S_ * B_ * K_];   // softmax emissions

// ---- packed dual-fp32 helpers (sm_103a f32x2 pipe) ----
static __device__ __forceinline__ unsigned long long ffma2_(
    unsigned long long a, unsigned long long b, unsigned long long c)
{
    unsigned long long d;
    asm("fma.rn.f32x2 %0, %1, %2, %3;" : "=l"(d) : "l"(a), "l"(b), "l"(c));
    return d;
}
static __device__ __forceinline__ unsigned long long addf2_(
    unsigned long long a, unsigned long long b)
{
    unsigned long long d;
    asm("add.rn.f32x2 %0, %1, %2;" : "=l"(d) : "l"(a), "l"(b));
    return d;
}
static __device__ __forceinline__ float lo_(unsigned long long v) {
    return __uint_as_float((unsigned)(v & 0xffffffffull));
}
static __device__ __forceinline__ float hi_(unsigned long long v) {
    return __uint_as_float((unsigned)(v >> 32));
}
static __device__ __forceinline__ unsigned long long pack2_(float lo, float hi) {
    unsigned long long r;
    asm("mov.b64 %0, {%1, %2};" : "=l"(r) : "f"(lo), "f"(hi));
    return r;
}
// predicated stores (single @p instruction, no BSSY/BSYNC envelope)
static __device__ __forceinline__ void sts_pred_(int pred, unsigned addr, float v) {
    asm volatile("{ .reg .pred p; setp.ne.s32 p, %0, 0; @p st.shared.f32 [%1], %2; }"
                 :: "r"(pred), "r"(addr), "f"(v));
}
static __device__ __forceinline__ void stg_pred_(int pred, float* ptr, float v) {
    asm volatile("{ .reg .pred p; setp.ne.s32 p, %0, 0; @p st.global.f32 [%1], %2; }"
                 :: "r"(pred), "l"(ptr), "f"(v));
}
static __device__ __forceinline__ unsigned smem_u32_(const void* p) {
    unsigned a;
    asm("{ .reg .u64 t; cvta.to.shared.u64 t, %1; cvt.u32.u64 %0, t; }" : "=r"(a) : "l"(p));
    return a;
}
static __device__ __forceinline__ void barn_(int id, int cnt) {
    asm volatile("bar.sync %0, %1;" :: "r"(id), "r"(cnt) : "memory");
}
// ---- mbarrier + 1D bulk-async copy (UBLKCP) ----
static __device__ __forceinline__ void mbar_init_(unsigned mbar, int cnt) {
    asm volatile("mbarrier.init.shared.b64 [%0], %1;" :: "r"(mbar), "r"(cnt) : "memory");
}
static __device__ __forceinline__ void mbar_expect_(unsigned mbar, unsigned bytes) {
    asm volatile("mbarrier.arrive.expect_tx.shared.b64 _, [%0], %1;"
                 :: "r"(mbar), "r"(bytes) : "memory");
}
static __device__ __forceinline__ void bulk_g2s_(unsigned dst, const void* src,
                                                 unsigned bytes, unsigned mbar) {
    asm volatile("cp.async.bulk.shared::cta.global.mbarrier::complete_tx::bytes "
                 "[%0], [%1], %2, [%3];"
                 :: "r"(dst), "l"(src), "r"(bytes), "r"(mbar) : "memory");
}
static __device__ __forceinline__ void mbar_wait_(unsigned mbar, unsigned phase) {
    unsigned done;
    asm volatile(
        "{\n\t.reg .pred p;\n\t"
        "mbarrier.try_wait.parity.acquire.cta.shared::cta.b64 p, [%1], %2;\n\t"
        "selp.b32 %0, 1, 0, p;\n\t}"
        : "=r"(done) : "r"(mbar), "r"(phase) : "memory");
    if (!done) {
        asm volatile(
            "{\n\t.reg .pred P1;\n\t"
            "WL_%=:\n\t"
            "mbarrier.try_wait.parity.acquire.cta.shared::cta.b64 P1, [%0], %1, 0x989680;\n\t"
            "@P1 bra.uni WD_%=;\n\t"
            "bra.uni WL_%=;\n\t"
            "WD_%=:\n\t}"
            :: "r"(mbar), "r"(phase) : "memory");
    }
}

// profiling-slot spacer (ncu captures the 4th app launch; make it proj)
__global__ void noop_kernel() {}

// =====================================================================
// Kernel 1: persistent input projection.
//   grid 148 = 2 dirs x 74 CTAs. Weights staged once. A tiles (64 rows,
//   contiguous 51712B, always 16B-aligned) arrive via ONE cp.async.bulk
//   per tile (mbarrier completion) -> zero per-element copy-issue cost.
//   A tile stored PACKED (202-float rows); inner loop reads A as LDS.64
//   pairs (8B-aligned for all rows, conflict-free), B as broadcast
//   LDS.128 from the padded-204 weight tile (zero pads kill tail pair).
// =====================================================================
#define PG_DIR  74
#define PG_G    148
#define PJ_T    640
#define TILE_BYTES 51712u                 // 64*202*4
#define OFF_A0  0                         // 12936 floats (12928 + slack)
#define OFF_A1  12936
#define OFF_B   25872                     // 100*204 = 20400 floats
#define OFF_EP  46272                     // 64*101  =  6464 floats
#define OFF_MB  52736                     // 2 mbarriers (16B)
#define PJ_SMEM ((OFF_MB + 8) * 4)        // 210976 bytes
#define NTILES  2048

__global__ __launch_bounds__(PJ_T, 1) void proj_kernel(
    const float* __restrict__ x,
    const float* __restrict__ Wf, const float* __restrict__ Wb,
    const float* __restrict__ bihf, const float* __restrict__ bhhf,
    const float* __restrict__ bihb, const float* __restrict__ bhhb)
{
    extern __shared__ __align__(16) float smf[];
    const int tid = threadIdx.x;
    const int dir = (blockIdx.x >= PG_DIR) ? 1 : 0;
    const int cid = blockIdx.x - dir * PG_DIR;   // 0..73
    const float* W   = dir ? Wb   : Wf;
    const float* bih = dir ? bihb : bihf;
    const float* bhh = dir ? bhhb : bhhf;

    const unsigned mb0 = smem_u32_(smf + OFF_MB);
    const unsigned mb1 = mb0 + 8;
    const unsigned ab0 = smem_u32_(smf + OFF_A0);
    const unsigned ab1 = smem_u32_(smf + OFF_A1);

    if (tid == 0) { mbar_init_(mb0, 1); mbar_init_(mb1, 1); }

    // stage this direction's weights ONCE (zero-padded to 204)
    for (int e = tid; e < 100 * 204; e += PJ_T) {
        int n = e / 204, f = e - n * 204;
        smf[OFF_B + e] = (f < F_) ? W[n * F_ + f] : 0.f;
    }
    __syncthreads();

    // prologue: one bulk copy for the first tile
    if (tid == 0) {
        mbar_expect_(mb0, TILE_BYTES);
        bulk_g2s_(ab0, x + (size_t)cid * 12928, TILE_BYTES, mb0);
    }

    const int tx = tid & 31;     // A rows tx, tx+32
    const int w  = tid >> 5;     // warp 0..19 -> cols w + 20*j
    float bias_j[5];
    #pragma unroll
    for (int j = 0; j < 5; j++) { int c = w + 20 * j; bias_j[j] = bih[c] + bhh[c]; }

    const ulonglong2* B2 = (const ulonglong2*)(smf + OFF_B);
    float* ep = smf + OFF_EP;

    int cur = 0;
    unsigned ph0 = 0, ph1 = 0;
    for (int mt = cid; mt < NTILES; mt += PG_DIR) {
        // issue next tile's bulk copy into the other buffer
        int nt = mt + PG_DIR;
        if (tid == 0 && nt < NTILES) {
            unsigned mbn = cur ? mb0 : mb1;
            unsigned abn = cur ? ab0 : ab1;
            mbar_expect_(mbn, TILE_BYTES);
            bulk_g2s_(abn, x + (size_t)nt * 12928, TILE_BYTES, mbn);
        }
        // wait for current tile
        if (cur == 0) { mbar_wait_(mb0, ph0); }
        else          { mbar_wait_(mb1, ph1); }

        const unsigned long long* A8 =
            (const unsigned long long*)(smf + (cur ? OFF_A1 : OFF_A0));
        const int rb0 = 101 * tx;          // pair-index base, row tx
        const int rb1 = 101 * (tx + 32);   // pair-index base, row tx+32

        unsigned long long acc2[2][5];
        #pragma unroll
        for (int i = 0; i < 2; i++)
            #pragma unroll
            for (int j = 0; j < 5; j++) acc2[i][j] = 0ull;

        #pragma unroll 3
        for (int kk = 0; kk < 51; kk++) {
            unsigned long long a00 = A8[rb0 + 2 * kk];
            unsigned long long a01 = A8[rb0 + 2 * kk + 1];
            unsigned long long a10 = A8[rb1 + 2 * kk];
            unsigned long long a11 = A8[rb1 + 2 * kk + 1];
            ulonglong2 b[5];
            #pragma unroll
            for (int j = 0; j < 5; j++) b[j] = B2[(w + 20 * j) * 51 + kk];
            #pragma unroll
            for (int j = 0; j < 5; j++) {
                acc2[0][j] = ffma2_(a00, b[j].x, acc2[0][j]);
                acc2[0][j] = ffma2_(a01, b[j].y, acc2[0][j]);
                acc2[1][j] = ffma2_(a10, b[j].x, acc2[1][j]);
                acc2[1][j] = ffma2_(a11, b[j].y, acc2[1][j]);
            }
        }
        if (cur == 0) ph0 ^= 1; else ph1 ^= 1;

        // stage outputs (odd stride 101 -> conflict-free), then coalesced STG
        #pragma unroll
        for (int j = 0; j < 5; j++) {
            int c = w + 20 * j;
            ep[tx * 101 + c]        = lo_(acc2[0][j]) + hi_(acc2[0][j]) + bias_j[j];
            ep[(tx + 32) * 101 + c] = lo_(acc2[1][j]) + hi_(acc2[1][j]) + bias_j[j];
        }
        __syncthreads();
        {
            float* gout = g_xp + (size_t)(mt * 64) * N2_ + dir * H_;
            #pragma unroll
            for (int q = 0; q < 10; q++) {
                int e = tid + q * PJ_T;           // 6400 exact
                int r = e / 100, c = e - r * 100;
                gout[(size_t)r * N2_ + c] = ep[r * 101 + c];
            }
        }
        __syncthreads();
        cur ^= 1;
    }
}

// =====================================================================
// Kernel 2: recurrent scans (REVERTED to the proven R7 version).
//   One CTA (128 thr) per (direction,batch) chain; weights in regs;
//   uniform control flow; predicated stores; MLP-4 xp prefetch.
// =====================================================================
__global__ __launch_bounds__(128) void rnn_kernel(
    const float* __restrict__ Whhf, const float* __restrict__ Whhb)
{
    const int chain = blockIdx.x;        // 0..255
    const int dir   = chain >> 7;        // 0 fwd, 1 bwd
    const int b     = chain & 127;
    const int j     = threadIdx.x;       // 0..127
    const int jc    = (j < H_) ? j : (H_ - 1);  // clamped lane
    const int act   = (j < H_) ? 1 : 0;

    __shared__ __align__(16) float hs[2][104];

    const float* Whh = dir ? Whhb : Whhf;
    unsigned long long w2[50];
    {
        const ulonglong2* wp = (const ulonglong2*)(Whh + jc * H_);
        #pragma unroll
        for (int k = 0; k < 25; k++) { ulonglong2 t = wp[k]; w2[2*k] = t.x; w2[2*k+1] = t.y; }
    }
    if (j < 104) { hs[0][j] = 0.f; hs[1][j] = 0.f; }

    // desync co-resident CTAs so their stall phases interleave
    if (chain & 1) __nanosleep(150);
    __syncthreads();

    const unsigned hs_base = smem_u32_(&hs[0][0]);
    const float* xpb = g_xp + (size_t)b * N2_ + dir * H_ + jc;
    float*       hgb = g_h  + (size_t)b * N2_ + dir * H_ + jc;
    const int s0 = dir ? (S_ - 1) : 0;
    const int ds = dir ? -1 : 1;
    const int STRIDE = B_ * N2_;  // 25600

    float xq[4];
    #pragma unroll
    for (int q = 0; q < 4; q++) xq[q] = xpb[(size_t)(s0 + ds * q) * STRIDE];

    int p = 0;
    #pragma unroll 4
    for (int t = 0; t < S_; t++) {
        const int s = s0 + ds * t;
        const float x0 = xq[t & 3];
        int tp = t + 4; tp = (tp < S_) ? tp : (S_ - 1);     // clamp, branch-free
        xq[t & 3] = xpb[(size_t)(s0 + ds * tp) * STRIDE];

        unsigned long long a[8];
        a[0] = pack2_(x0, 0.f);
        #pragma unroll
        for (int q = 1; q < 8; q++) a[q] = 0ull;

        const ulonglong2* hv2 = (const ulonglong2*)hs[p];
        #pragma unroll
        for (int k = 0; k < 25; k++) {
            ulonglong2 h2 = hv2[k];
            a[(2*k)     & 7] = ffma2_(w2[2*k],     h2.x, a[(2*k)     & 7]);
            a[(2*k + 1) & 7] = ffma2_(w2[2*k + 1], h2.y, a[(2*k + 1) & 7]);
        }
        unsigned long long r0 = addf2_(addf2_(a[0], a[4]), addf2_(a[1], a[5]));
        unsigned long long r1 = addf2_(addf2_(a[2], a[6]), addf2_(a[3], a[7]));
        unsigned long long rr = addf2_(r0, r1);
        float acc = lo_(rr) + hi_(rr);

        // tanh(x) = 1 - 2/(e^{2x}+1); inf-safe, ~1e-7 abs err
        float e2 = __expf(acc + acc);
        float hn = 1.f - __fdividef(2.f, e2 + 1.f);

        sts_pred_(act, hs_base + (unsigned)((p ^ 1) * 104 + j) * 4u, hn);
        stg_pred_(act, hgb + (size_t)s * STRIDE, hn);
        __syncthreads();
        p ^= 1;
    }
}

// =====================================================================
// Kernel 3: logits + softmax -> emissions. Thread per (s,b) row.
// =====================================================================
__global__ __launch_bounds__(256) void logits_kernel(
    const float* __restrict__ Wout, const float* __restrict__ bout)
{
    __shared__ __align__(16) float wt[N2_ * 20];   // W_out^T, K padded 19->20
    const int tid = threadIdx.x;
    for (int e = tid; e < N2_ * 20; e += 256) {
        int f = e / 20, k = e - f * 20;
        wt[e] = (k < K_) ? Wout[k * N2_ + f] : 0.f;
    }
    __syncthreads();

    const int m = blockIdx.x * 256 + tid;
    const float4* hp = (const float4*)(g_h + (size_t)m * N2_);
    const ulonglong2* wt2 = (const ulonglong2*)wt;

    unsigned long long acc2[10];
    #pragma unroll
    for (int q = 0; q < 10; q++) acc2[q] = 0ull;

    for (int f4 = 0; f4 < 50; f4++) {
        float4 hv = __ldg(&hp[f4]);
        float hh[4] = {hv.x, hv.y, hv.z, hv.w};
        #pragma unroll
        for (int c = 0; c < 4; c++) {
            const int f = f4 * 4 + c;
            const unsigned long long hb = pack2_(hh[c], hh[c]);
            #pragma unroll
            for (int q = 0; q < 5; q++) {
                ulonglong2 wv = wt2[f * 5 + q];
                acc2[2*q]     = ffma2_(hb, wv.x, acc2[2*q]);
                acc2[2*q + 1] = ffma2_(hb, wv.y, acc2[2*q + 1]);
            }
        }
    }

    float acc[20];
    #pragma unroll
    for (int q = 0; q < 10; q++) { acc[2*q] = lo_(acc2[q]); acc[2*q+1] = hi_(acc2[q]); }

    float mx = -1e30f;
    #pragma unroll
    for (int k = 0; k < K_; k++) { acc[k] += __ldg(&bout[k]); mx = fmaxf(mx, acc[k]); }
    float sum = 0.f;
    #pragma unroll
    for (int k = 0; k < K_; k++) { acc[k] = __expf(acc[k] - mx); sum += acc[k]; }
    const float inv = 1.f / sum;
    float* e = g_em + (size_t)m * K_;
    #pragma unroll
    for (int k = 0; k < K_; k++) e[k] = acc[k] * inv;
}

// =====================================================================
// Kernel 4: Viterbi decode. Warp per sequence; tie-stable tree argmax.
// =====================================================================
__global__ __launch_bounds__(256) void viterbi_kernel(
    const float* __restrict__ start, const float* __restrict__ endt,
    const float* __restrict__ trans, float* __restrict__ out)
{
    __shared__ unsigned char hist[8][127][20];
    const int w    = threadIdx.x >> 5;
    const int lane = threadIdx.x & 31;
    const int n    = blockIdx.x * 8 + w;
    const int j    = lane;
    const bool act = (j < K_);

    float tr[K_];
    #pragma unroll
    for (int i = 0; i < K_; i++) tr[i] = act ? trans[i * K_ + j] : 0.f;

    const float* emn = g_em + (size_t)n * B_ * K_;
    float score = act ? (start[j] + emn[j]) : -1e30f;

    for (int t = 1; t < B_; t++) {
        const float e = act ? emn[t * K_ + j] : 0.f;
        float bv[K_]; int bi[K_];
        #pragma unroll
        for (int i = 0; i < K_; i++) {
            float si = __shfl_sync(0xffffffffu, score, i);
            bv[i] = si + tr[i];
            bi[i] = i;
        }
        // tie-stable tree argmax: strict > keeps the LOWER index on ties
        #pragma unroll
        for (int st = 1; st < 32; st <<= 1)
            #pragma unroll
            for (int i = 0; i + st < K_; i += 2 * st) {
                bool take = (bv[i + st] > bv[i]);
                bv[i] = take ? bv[i + st] : bv[i];
                bi[i] = take ? bi[i + st] : bi[i];
            }
        if (act) hist[w][t - 1][j] = (unsigned char)bi[0];
        score = bv[0] + e;
    }

    float v  = act ? (score + endt[j]) : -1e30f;
    int  idx = j;
    #pragma unroll
    for (int off = 16; off; off >>= 1) {
        float ov = __shfl_down_sync(0xffffffffu, v, off);
        int   oi = __shfl_down_sync(0xffffffffu, idx, off);
        if (ov > v || (ov == v && oi < idx)) { v = ov; idx = oi; }
    }
    __syncwarp();

    if (lane == 0) {
        int tag = idx;
        float* o = out + (size_t)n * B_;
        o[B_ - 1] = (float)tag;
        for (int t = B_ - 2; t >= 0; t--) {
            tag  = hist[w][t][tag];
            o[t] = (float)tag;
        }
    }
}

// =====================================================================
extern "C" void kernel_launch(void* const* d_in, const int* in_sizes, int n_in,
                              void* d_out, int out_size)
{
    const float* x     = (const float*)d_in[0];
    const float* Wihf  = (const float*)d_in[1];
    const float* Whhf  = (const float*)d_in[2];
    const float* bihf  = (const float*)d_in[3];
    const float* bhhf  = (const float*)d_in[4];
    const float* Wihb  = (const float*)d_in[5];
    const float* Whhb  = (const float*)d_in[6];
    const float* bihb  = (const float*)d_in[7];
    const float* bhhb  = (const float*)d_in[8];
    const float* Wout  = (const float*)d_in[9];
    const float* bout  = (const float*)d_in[10];
    const float* start = (const float*)d_in[11];
    const float* endt  = (const float*)d_in[12];
    const float* trans = (const float*)d_in[13];
    float* out = (float*)d_out;

    cudaFuncSetAttribute(proj_kernel, cudaFuncAttributeMaxDynamicSharedMemorySize, PJ_SMEM);

    // spacers: put proj_kernel in the ncu capture slot (4th app launch)
    noop_kernel<<<1, 32>>>();
    noop_kernel<<<1, 32>>>();
    noop_kernel<<<1, 32>>>();
    proj_kernel<<<PG_G, PJ_T, PJ_SMEM>>>(x, Wihf, Wihb, bihf, bhhf, bihb, bhhb);
    rnn_kernel<<<2 * B_, 128>>>(Whhf, Whhb);
    logits_kernel<<<(S_ * B_) / 256, 256>>>(Wout, bout);
    viterbi_kernel<<<S_ / 8, 256>>>(start, endt, trans, out);
}